// round 7
// baseline (speedup 1.0000x reference)
#include <cuda_runtime.h>

// Online Normalization forward, fused persistent kernel (v7: 148-CTA full-chip).
// x: [B=32, H=64, W=64, C=256] channels-last, fp32.
//
// 148 CTAs x 1024 threads, one per SM (co-resident -> grid barrier safe).
// Rows (131072 total) are split into 148 contiguous chunks (886/885 rows);
// a chunk spans at most 2 batches -> pass 1 accumulates two sequential
// segments into per-slot gmem partials. One grid barrier. Staging folds the
// slot partials per batch (deterministic order), a 32-step EMA scan fills
// smem mu/rs for all batches, then pass 3 re-reads the chunk (L2 hits,
// reverse order) and writes with streaming stores.

#define AFWD 0.999f
#define EPS  1e-5f

constexpr int Bn    = 32;
constexpr int HW    = 64 * 64;          // 4096 rows per batch
constexpr int Cc    = 256;
constexpr int C4    = Cc / 4;           // 64
constexpr int NCTA  = 148;
constexpr int TROWS = Bn * HW;          // 131072 total rows
constexpr int BIGC  = TROWS % NCTA;     // 92 chunks get an extra row
constexpr int BASEL = TROWS / NCTA;     // 885

__device__ float g_ps[NCTA * 2 * Cc];   // per-slot segment sums
__device__ float g_pq[NCTA * 2 * Cc];   // per-slot segment sum-squares
__device__ unsigned long long g_bar;    // monotonic across graph replays

// Dynamic smem (floats):
//   [0 : 16384)      union: pass1 reduce (red_s 0:4096, red_q 4096:8192)
//                            staging (st_s 0:8192, st_q 8192:16384)
//   [16384 : 24576)  sm_mu  [32 batches x 256 c]
//   [24576 : 32768)  sm_rs
constexpr int SMEM_FLOATS = 32768;      // 128 KB

__device__ __forceinline__ int chunk_r0(int j) {
    return j * BASEL + (j < BIGC ? j : BIGC);
}

__device__ __forceinline__ void grid_barrier() {
    __syncthreads();
    if (threadIdx.x == 0) {
        __threadfence();
        unsigned long long t = atomicAdd(&g_bar, 1ULL) + 1ULL;
        unsigned long long target = ((t + NCTA - 1ULL) / NCTA) * NCTA;
        while (*((volatile unsigned long long*)&g_bar) < target) { }
        __threadfence();
    }
    __syncthreads();
}

__global__ __launch_bounds__(1024, 1)
void onorm_fused(const float4* __restrict__ x4,
                 float4* __restrict__ o4,
                 const float* __restrict__ mu0,
                 const float* __restrict__ var0) {
    extern __shared__ float sm[];
    float* red_s = sm;                  // 4096 floats
    float* red_q = sm + 4096;           // 4096 floats
    float* st_s  = sm;                  // 8192 floats (after barrier)
    float* st_q  = sm + 8192;           // 8192 floats
    float* sm_mu = sm + 16384;          // 8192 floats
    float* sm_rs = sm + 24576;          // 8192 floats

    const int tid = threadIdx.x;
    const int j   = blockIdx.x;         // chunk / slot id
    const int c4  = tid & 63;           // float4 channel index
    const int rg  = tid >> 6;           // 0..15 row group

    const int r0 = chunk_r0(j);
    const int r1 = chunk_r0(j + 1);
    const int b0 = r0 >> 12;            // first batch in chunk
    const int rsplit = min(r1, (b0 + 1) << 12);
    const bool hasB = (rsplit < r1);    // chunk spans a second batch
    const int base = r0 + rg;

    // ---------------- Pass 1: segment A (batch b0) ----------------
    {
        float4 a = {0.f,0.f,0.f,0.f}, q = {0.f,0.f,0.f,0.f};
        #pragma unroll 8
        for (int row = base; row < rsplit; row += 16) {
            float4 v = x4[(size_t)row * C4 + c4];
            a.x += v.x; a.y += v.y; a.z += v.z; a.w += v.w;
            q.x = fmaf(v.x, v.x, q.x); q.y = fmaf(v.y, v.y, q.y);
            q.z = fmaf(v.z, v.z, q.z); q.w = fmaf(v.w, v.w, q.w);
        }
        ((float4*)red_s)[rg * 64 + c4] = a;
        ((float4*)red_q)[rg * 64 + c4] = q;
        __syncthreads();
        if (tid < 64) {
            float4 sa = {0.f,0.f,0.f,0.f}, sq = {0.f,0.f,0.f,0.f};
            #pragma unroll
            for (int k = 0; k < 16; k++) {
                float4 va = ((float4*)red_s)[k * 64 + tid];
                float4 vq = ((float4*)red_q)[k * 64 + tid];
                sa.x += va.x; sa.y += va.y; sa.z += va.z; sa.w += va.w;
                sq.x += vq.x; sq.y += vq.y; sq.z += vq.z; sq.w += vq.w;
            }
            ((float4*)g_ps)[(2 * j + 0) * 64 + tid] = sa;
            ((float4*)g_pq)[(2 * j + 0) * 64 + tid] = sq;
        }
        __syncthreads();
    }

    // ---------------- Pass 1: segment B (batch b0+1), if any ----------------
    if (hasB) {
        const int startB = (base >= rsplit)
                         ? base
                         : base + ((rsplit - base + 15) >> 4) * 16;
        float4 a = {0.f,0.f,0.f,0.f}, q = {0.f,0.f,0.f,0.f};
        #pragma unroll 8
        for (int row = startB; row < r1; row += 16) {
            float4 v = x4[(size_t)row * C4 + c4];
            a.x += v.x; a.y += v.y; a.z += v.z; a.w += v.w;
            q.x = fmaf(v.x, v.x, q.x); q.y = fmaf(v.y, v.y, q.y);
            q.z = fmaf(v.z, v.z, q.z); q.w = fmaf(v.w, v.w, q.w);
        }
        ((float4*)red_s)[rg * 64 + c4] = a;
        ((float4*)red_q)[rg * 64 + c4] = q;
        __syncthreads();
        if (tid < 64) {
            float4 sa = {0.f,0.f,0.f,0.f}, sq = {0.f,0.f,0.f,0.f};
            #pragma unroll
            for (int k = 0; k < 16; k++) {
                float4 va = ((float4*)red_s)[k * 64 + tid];
                float4 vq = ((float4*)red_q)[k * 64 + tid];
                sa.x += va.x; sa.y += va.y; sa.z += va.z; sa.w += va.w;
                sq.x += vq.x; sq.y += vq.y; sq.z += vq.z; sq.w += vq.w;
            }
            ((float4*)g_ps)[(2 * j + 1) * 64 + tid] = sa;
            ((float4*)g_pq)[(2 * j + 1) * 64 + tid] = sq;
        }
        __syncthreads();
    }

    grid_barrier();     // partials visible; red area retired for staging reuse

    // ------- Staging: fold slot partials per (batch, channel), fixed order ----
    // pair i -> tt = i>>8, c = i&255. Each batch intersects <= 6 chunks.
    for (int i = tid; i < Bn * Cc; i += 1024) {
        const int tt = i >> 8;
        const int c  = i & 255;
        const int R  = tt << 12;
        int jj = (R - 978) / 886;       // conservative under-estimate, >= 0 ok
        if (jj < 0) jj = 0;
        while (chunk_r0(jj + 1) <= R) jj++;     // first chunk intersecting tt
        float s = 0.f, s2 = 0.f;
        for (; jj < NCTA && chunk_r0(jj) < R + HW; jj++) {
            const int seg = ((chunk_r0(jj) >> 12) == tt) ? 0 : 1;
            s  += g_ps[(2 * jj + seg) * Cc + c];
            s2 += g_pq[(2 * jj + seg) * Cc + c];
        }
        st_s[i] = s;
        st_q[i] = s2;
    }
    __syncthreads();

    // ------------- Scan: 32-step EMA recurrence, all batches into smem --------
    if (tid < Cc) {
        const int c = tid;
        float mu  = mu0[c];
        float var = var0[c];
        const float inv = 1.0f / (float)HW;
        #pragma unroll
        for (int tt = 0; tt < Bn; tt++) {
            sm_mu[tt * Cc + c] = mu;
            sm_rs[tt * Cc + c] = rsqrtf(var + EPS);
            const float mean = st_s[tt * Cc + c] * inv;
            const float vart = fmaf(-mean, mean, st_q[tt * Cc + c] * inv);
            const float d    = mean - mu;
            var = AFWD * var + (1.0f - AFWD) * vart
                + AFWD * (1.0f - AFWD) * d * d;
            mu  = fmaf(1.0f - AFWD, d, mu);
        }
    }
    __syncthreads();

    // ---------------- Pass 3: normalize chunk (reverse order, L2 hits) --------
    // Segment B first (later rows were read more recently), then segment A.
    if (hasB) {
        const float4 m = ((const float4*)sm_mu)[(b0 + 1) * 64 + c4];
        const float4 r = ((const float4*)sm_rs)[(b0 + 1) * 64 + c4];
        const int last = base + (((r1 - 1 - base) >> 4) << 4);
        #pragma unroll 8
        for (int row = last; row >= rsplit; row -= 16) {
            float4 v = x4[(size_t)row * C4 + c4];
            float4 w;
            w.x = (v.x - m.x) * r.x;
            w.y = (v.y - m.y) * r.y;
            w.z = (v.z - m.z) * r.z;
            w.w = (v.w - m.w) * r.w;
            __stcs(&o4[(size_t)row * C4 + c4], w);
        }
    }
    if (base < rsplit) {
        const float4 m = ((const float4*)sm_mu)[b0 * 64 + c4];
        const float4 r = ((const float4*)sm_rs)[b0 * 64 + c4];
        const int last = base + (((rsplit - 1 - base) >> 4) << 4);
        #pragma unroll 8
        for (int row = last; row >= base; row -= 16) {
            float4 v = x4[(size_t)row * C4 + c4];
            float4 w;
            w.x = (v.x - m.x) * r.x;
            w.y = (v.y - m.y) * r.y;
            w.z = (v.z - m.z) * r.z;
            w.w = (v.w - m.w) * r.w;
            __stcs(&o4[(size_t)row * C4 + c4], w);
        }
    }
}

extern "C" void kernel_launch(void* const* d_in, const int* in_sizes, int n_in,
                              void* d_out, int out_size) {
    const float* x    = (const float*)d_in[0];
    const float* mu0  = (const float*)d_in[1];
    const float* var0 = (const float*)d_in[2];
    float* out = (float*)d_out;

    static bool attr_set = false;
    if (!attr_set) {
        cudaFuncSetAttribute(onorm_fused,
                             cudaFuncAttributeMaxDynamicSharedMemorySize,
                             SMEM_FLOATS * sizeof(float));
        attr_set = true;
    }

    onorm_fused<<<NCTA, 1024, SMEM_FLOATS * sizeof(float)>>>(
        (const float4*)x, (float4*)out, mu0, var0);
}

// round 8
// speedup vs baseline: 1.3323x; 1.3323x over previous
#include <cuda_runtime.h>

// Online Normalization forward, fused persistent kernel (v8).
// x: [B=32, H=64, W=64, C=256] channels-last, fp32.
//
// 256 CTAs x 512 threads (2 CTAs/SM co-resident -> grid barrier safe, all
// 148 SMs active). CTA (t*8+s) owns 512-row chunk s of batch t (512 KB).
// All loops static and power-of-2 (v7 lesson: dynamic bounds kill MLP).
// Pass 1: sync-free register accumulation + one smem reduce -> gmem partials.
// One grid barrier. Bulk smem staging folds the 8 chunk-partials per batch,
// per-CTA scan runs the EMA recurrence up to its own batch. Pass 3:
// reverse-order re-read of own chunk (L2 hits), streaming stores.

#define AFWD 0.999f
#define EPS  1e-5f

constexpr int Bn   = 32;
constexpr int HW   = 64 * 64;       // 4096 rows per batch
constexpr int Cc   = 256;
constexpr int C4   = Cc / 4;        // 64
constexpr int NCTA = 256;           // 32 batches x 8 chunks
constexpr int TPB  = 512;
constexpr int ROWS = 512;           // rows per chunk
constexpr int RG   = TPB / C4;      // 8 row groups
constexpr int ITER = ROWS / RG;     // 64 rows per thread

__device__ float g_ps[NCTA * Cc];   // per-chunk partial sums
__device__ float g_pq[NCTA * Cc];   // per-chunk partial sum-squares
__device__ unsigned long long g_bar;   // monotonic across graph replays

// Dynamic smem (floats):
//   [0 : 16384)   union: pass1 reduce (red_s 0:2048, red_q 2048:4096)
//                         staging (st_s 0:8192, st_q 8192:16384)
//   [16384:16640) sm_mu (own batch)
//   [16640:16896) sm_rs (own batch)
constexpr int SMEM_FLOATS = 16896;  // 67.6 KB  (x2 CTA/SM = 135 KB <= 228 KB)

__device__ __forceinline__ void grid_barrier() {
    __syncthreads();
    if (threadIdx.x == 0) {
        __threadfence();
        unsigned long long t = atomicAdd(&g_bar, 1ULL) + 1ULL;
        unsigned long long target = ((t + NCTA - 1ULL) / NCTA) * NCTA;
        while (*((volatile unsigned long long*)&g_bar) < target) { }
        __threadfence();
    }
    __syncthreads();
}

__global__ __launch_bounds__(TPB, 2)
void onorm_fused(const float4* __restrict__ x4,
                 float4* __restrict__ o4,
                 const float* __restrict__ mu0,
                 const float* __restrict__ var0) {
    extern __shared__ float sm[];
    float* red_s = sm;                 // 2048 floats
    float* red_q = sm + 2048;          // 2048 floats
    float* st_s  = sm;                 // 8192 floats (after barrier)
    float* st_q  = sm + 8192;          // 8192 floats
    float* sm_mu = sm + 16384;         // 256 floats
    float* sm_rs = sm + 16640;         // 256 floats

    const int tid = threadIdx.x;
    const int cta = blockIdx.x;
    const int c4  = tid & 63;          // float4 channel index
    const int rg  = tid >> 6;          // 0..7 row group
    const int t   = cta >> 3;          // batch owned by this CTA
    const int s   = cta & 7;           // chunk within the batch

    const size_t base = ((size_t)t * HW + (size_t)s * ROWS + rg) * C4;
    const float4* p = x4 + base + c4;

    // ---------------- Pass 1: sync-free streaming accumulation ----------------
    float4 a = {0.f,0.f,0.f,0.f}, q = {0.f,0.f,0.f,0.f};
    #pragma unroll 8
    for (int i = 0; i < ITER; i++) {
        float4 v = p[(size_t)i * RG * C4];
        a.x += v.x; a.y += v.y; a.z += v.z; a.w += v.w;
        q.x = fmaf(v.x, v.x, q.x); q.y = fmaf(v.y, v.y, q.y);
        q.z = fmaf(v.z, v.z, q.z); q.w = fmaf(v.w, v.w, q.w);
    }
    ((float4*)red_s)[rg * 64 + c4] = a;
    ((float4*)red_q)[rg * 64 + c4] = q;
    __syncthreads();
    if (tid < 64) {
        float4 sa = {0.f,0.f,0.f,0.f}, sq = {0.f,0.f,0.f,0.f};
        #pragma unroll
        for (int j = 0; j < RG; j++) {
            float4 va = ((float4*)red_s)[j * 64 + tid];
            float4 vq = ((float4*)red_q)[j * 64 + tid];
            sa.x += va.x; sa.y += va.y; sa.z += va.z; sa.w += va.w;
            sq.x += vq.x; sq.y += vq.y; sq.z += vq.z; sq.w += vq.w;
        }
        ((float4*)g_ps)[cta * 64 + tid] = sa;
        ((float4*)g_pq)[cta * 64 + tid] = sq;
    }

    grid_barrier();   // partials visible; red area retired for staging reuse

    // ------- Staging: fold the 8 chunk-partials per earlier batch -------------
    // i encodes (tt, c): tt = i>>8, c = i&255. Only batches < t are needed.
    for (int i = tid; i < t * Cc; i += TPB) {
        const int b = ((i >> 8) << 11) + (i & 255);   // (tt*8)*Cc + c
        float ss = 0.f, qq = 0.f;
        #pragma unroll
        for (int k = 0; k < 8; k++) {
            ss += g_ps[b + k * Cc];
            qq += g_pq[b + k * Cc];
        }
        st_s[i] = ss;
        st_q[i] = qq;
    }
    __syncthreads();

    // ------------- Scan: EMA recurrence from smem, up to own batch ------------
    if (tid < Cc) {
        const int c = tid;
        float mu  = mu0[c];
        float var = var0[c];
        const float inv = 1.0f / (float)HW;
        for (int tt = 0; tt < t; tt++) {
            const float mean = st_s[tt * Cc + c] * inv;
            const float vart = fmaf(-mean, mean, st_q[tt * Cc + c] * inv);
            const float d    = mean - mu;
            var = AFWD * var + (1.0f - AFWD) * vart
                + AFWD * (1.0f - AFWD) * d * d;
            mu  = fmaf(1.0f - AFWD, d, mu);
        }
        sm_mu[c] = mu;
        sm_rs[c] = rsqrtf(var + EPS);
    }
    __syncthreads();

    // ---------------- Pass 3: normalize own chunk (reverse order) -------------
    const float4 m = ((const float4*)sm_mu)[c4];
    const float4 r = ((const float4*)sm_rs)[c4];
    float4* o = o4 + base + c4;
    #pragma unroll 8
    for (int i = ITER - 1; i >= 0; i--) {
        float4 v = p[(size_t)i * RG * C4];
        float4 w;
        w.x = (v.x - m.x) * r.x;
        w.y = (v.y - m.y) * r.y;
        w.z = (v.z - m.z) * r.z;
        w.w = (v.w - m.w) * r.w;
        __stcs(&o[(size_t)i * RG * C4], w);
    }
}

extern "C" void kernel_launch(void* const* d_in, const int* in_sizes, int n_in,
                              void* d_out, int out_size) {
    const float* x    = (const float*)d_in[0];
    const float* mu0  = (const float*)d_in[1];
    const float* var0 = (const float*)d_in[2];
    float* out = (float*)d_out;

    static bool attr_set = false;
    if (!attr_set) {
        cudaFuncSetAttribute(onorm_fused,
                             cudaFuncAttributeMaxDynamicSharedMemorySize,
                             SMEM_FLOATS * sizeof(float));
        attr_set = true;
    }

    onorm_fused<<<NCTA, TPB, SMEM_FLOATS * sizeof(float)>>>(
        (const float4*)x, (float4*)out, mu0, var0);
}